// round 8
// baseline (speedup 1.0000x reference)
#include <cuda_runtime.h>
#include <math.h>
#include <stdint.h>

// Problem shapes (fixed for this bench)
#define BB 4
#define TT 512
#define SS 1024
#define HH 768
#define VV 50257

// Vocab split: FOUR CTAs per (b,t) row (512 threads each -> 4 CTAs/SM).
// Quarter q covers [ (q*VV)>>2, ((q+1)*VV)>>2 ); max quarter size 12565.
#define VPADQ  12568                 // pad(<=3) + 12565, rounded to mult of 4
#define SMEM_FLOATS (VPADQ + 16)
#define SMEM_BYTES  (SMEM_FLOATS * 4)
#define NTHR 512

// Scratch for the collapsed p_gen projections (device globals: no allocation).
__device__ float g_u[BB * SS];   // u[b,s] = src[b,s,:] . W_pgen[:H]
__device__ float g_v[BB * TT];   // v[b,t] = tgt[b,t,:] . W_pgen[H:] + bias

// ---------------------------------------------------------------------------
// Kernel 1: tiny projections. One warp per row (B*S + B*T = 6144 rows).
// Triggers programmatic launch completion immediately so the copy kernel can
// begin its g_u-independent phases concurrently.
// ---------------------------------------------------------------------------
__global__ void pgen_prep_kernel(const float* __restrict__ src,
                                 const float* __restrict__ tgt,
                                 const float* __restrict__ W,
                                 const float* __restrict__ bias)
{
#if __CUDA_ARCH__ >= 900
    cudaTriggerProgrammaticLaunchCompletion();
#endif
    const int warp = (blockIdx.x * blockDim.x + threadIdx.x) >> 5;
    const int lane = threadIdx.x & 31;
    const int NU = BB * SS;
    const int NV = BB * TT;

    if (warp < NU) {
        const float4* x = reinterpret_cast<const float4*>(src + (size_t)warp * HH);
        const float4* w = reinterpret_cast<const float4*>(W);
        float acc = 0.f;
        #pragma unroll
        for (int j = lane; j < HH / 4; j += 32) {
            float4 a = x[j], b = w[j];
            acc += a.x * b.x + a.y * b.y + a.z * b.z + a.w * b.w;
        }
        #pragma unroll
        for (int o = 16; o; o >>= 1) acc += __shfl_xor_sync(0xffffffffu, acc, o);
        if (lane == 0) g_u[warp] = acc;
    } else if (warp < NU + NV) {
        const int r = warp - NU;
        const float4* x = reinterpret_cast<const float4*>(tgt + (size_t)r * HH);
        const float4* w = reinterpret_cast<const float4*>(W + HH);
        float acc = 0.f;
        #pragma unroll
        for (int j = lane; j < HH / 4; j += 32) {
            float4 a = x[j], b = w[j];
            acc += a.x * b.x + a.y * b.y + a.z * b.z + a.w * b.w;
        }
        #pragma unroll
        for (int o = 16; o; o >>= 1) acc += __shfl_xor_sync(0xffffffffu, acc, o);
        if (lane == 0) g_v[r] = acc + bias[0];
    }
}

// ---------------------------------------------------------------------------
// Kernel 2: four CTAs per (b,t) row, each owning a vocab quarter (~50KB smem,
// 512 threads -> 4 CTAs/SM = 4 concurrent TMA bulk-groups per SM).
//   Phase 1: zero smem accumulator (STS.128)
//   Phase 2: range-predicated shared atomicAdd scatter (2 src positions/thread)
//   Phase 3: ONE bulk-async (TMA) copy smem -> gmem for the quarter-row
//   Phase 4 (quarter 0 only): grid-dep sync on prep, fused p_gen reduction —
//            overlapped with this CTA's own TMA drain.
// ---------------------------------------------------------------------------
__global__ __launch_bounds__(NTHR, 4)
void copy_logits_kernel(const int* __restrict__ ids,
                        const float* __restrict__ attn,
                        float* __restrict__ out_pgen,
                        float* __restrict__ out_logits)
{
    extern __shared__ float sm[];          // [VPADQ] accumulator + [16] reduce
    const int row = blockIdx.x >> 2;       // b*T + t
    const int q   = blockIdx.x & 3;
    const int b   = row / TT;
    const int tid = threadIdx.x;

    const int lo = (q * VV) >> 2;
    const int hi = ((q + 1) * VV) >> 2;
    const int n  = hi - lo;

    // Global destination of this quarter-row; 16B phase decides head & pad.
    float* dst = out_logits + (size_t)row * VV + lo;
    const int head = (int)(((16u - ((uint32_t)(uintptr_t)dst & 15u)) & 15u) >> 2); // 0..3
    const int pad  = (4 - head) & 3;       // sm[pad+head] is 16B-aligned

    // Phase 1: zero the accumulator (vectorized STS.128).
    float4* sm4 = reinterpret_cast<float4*>(sm);
    const float4 z4 = make_float4(0.f, 0.f, 0.f, 0.f);
    #pragma unroll
    for (int i = tid; i < VPADQ / 4; i += NTHR) sm4[i] = z4;
    __syncthreads();

    // Phase 2: range-predicated scatter-add; each thread covers 2 positions.
    const float a0  = attn[(size_t)row * SS + tid];
    const float a1  = attn[(size_t)row * SS + tid + NTHR];
    const int   id0 = ids[b * SS + tid];
    const int   id1 = ids[b * SS + tid + NTHR];
    if (id0 >= lo && id0 < hi) atomicAdd(&sm[pad + id0 - lo], a0);
    if (id1 >= lo && id1 < hi) atomicAdd(&sm[pad + id1 - lo], a1);
    __syncthreads();   // all atomics complete

    // Phase 3: head/tail scalars + one bulk-async copy for the aligned middle.
    const int nvec = (n - head) >> 2;          // 16B chunks in the middle
    const int tail = head + 4 * nvec;

    if (tid < head)     __stcs(dst + tid, sm[pad + tid]);
    if (tid < n - tail) __stcs(dst + tail + tid, sm[pad + tail + tid]);

    if (tid == 0) {
        // Order generic-proxy smem writes (STS/ATOMS) before async-proxy read.
        asm volatile("fence.proxy.async.shared::cta;" ::: "memory");
        uint32_t saddr;
        asm("{ .reg .u64 t; cvta.to.shared.u64 t, %1; cvt.u32.u64 %0, t; }"
            : "=r"(saddr) : "l"(sm + pad + head));
        asm volatile(
            "cp.async.bulk.global.shared::cta.bulk_group [%0], [%1], %2;"
            :: "l"(dst + head), "r"(saddr), "r"(16 * nvec) : "memory");
        asm volatile("cp.async.bulk.commit_group;" ::: "memory");
    }

    // Phase 4: fused p_gen = sigmoid(attn . u + v), quarter-0 CTAs only.
    // Runs while this CTA's TMA drain is in flight. Requires prep complete.
    if (q == 0) {
#if __CUDA_ARCH__ >= 900
        cudaGridDependencySynchronize();
#endif
        float part = a0 * g_u[b * SS + tid] + a1 * g_u[b * SS + tid + NTHR];
        #pragma unroll
        for (int o = 16; o; o >>= 1) part += __shfl_xor_sync(0xffffffffu, part, o);
        float* red = sm + VPADQ;
        if ((tid & 31) == 0) red[tid >> 5] = part;
        __syncthreads();
        if (tid < 16) {
            float x = red[tid];
            #pragma unroll
            for (int o = 8; o; o >>= 1) x += __shfl_xor_sync(0xffffu, x, o);
            if (tid == 0) {
                const float zv = x + g_v[row];
                out_pgen[row] = 1.f / (1.f + __expf(-zv));
            }
        }
    }

    if (tid == 0)
        asm volatile("cp.async.bulk.wait_group 0;" ::: "memory");
}

// ---------------------------------------------------------------------------
// Launch: prep, then copy with Programmatic Dependent Launch so copy's
// g_u-independent phases overlap prep. Fallback to plain launch on error.
// ---------------------------------------------------------------------------
extern "C" void kernel_launch(void* const* d_in, const int* in_sizes, int n_in,
                              void* d_out, int out_size)
{
    const int*   ids  = (const int*)  d_in[0];  // [B,S] int32
    const float* attn = (const float*)d_in[1];  // [B,T,S]
    const float* src  = (const float*)d_in[2];  // [B,S,H]
    const float* tgt  = (const float*)d_in[3];  // [B,T,H]
    const float* W    = (const float*)d_in[4];  // [2H,1]
    const float* bias = (const float*)d_in[5];  // [1]

    float* out_pgen   = (float*)d_out;              // [B,T]  (first output)
    float* out_logits = out_pgen + (size_t)BB * TT; // [B,T,V]

    cudaFuncSetAttribute(copy_logits_kernel,
                         cudaFuncAttributeMaxDynamicSharedMemorySize,
                         SMEM_BYTES);

    pgen_prep_kernel<<<(BB * SS + BB * TT) / 8, 256>>>(src, tgt, W, bias);

    // Copy kernel with PDL (programmatic stream serialization).
    cudaLaunchConfig_t cfg = {};
    cfg.gridDim          = dim3(BB * TT * 4, 1, 1);
    cfg.blockDim         = dim3(NTHR, 1, 1);
    cfg.dynamicSmemBytes = SMEM_BYTES;
    cfg.stream           = 0;
    cudaLaunchAttribute attr[1];
    attr[0].id = cudaLaunchAttributeProgrammaticStreamSerialization;
    attr[0].val.programmaticStreamSerializationAllowed = 1;
    cfg.attrs    = attr;
    cfg.numAttrs = 1;

    cudaError_t e = cudaLaunchKernelEx(&cfg, copy_logits_kernel,
                                       ids, attn, out_pgen, out_logits);
    if (e != cudaSuccess) {
        (void)cudaGetLastError();   // clear; fall back to plain launch
        copy_logits_kernel<<<BB * TT * 4, NTHR, SMEM_BYTES>>>(ids, attn,
                                                              out_pgen,
                                                              out_logits);
    }
}